// round 7
// baseline (speedup 1.0000x reference)
#include <cuda_runtime.h>
#include <float.h>

#define BATCH 2
#define SEQ   4096
#define DIM   384
#define HEADS 6
#define HD    64
#define QK_SCALE 0.125f

__device__ float g_q[BATCH * HEADS * SEQ * HD];
__device__ float g_k[BATCH * HEADS * SEQ * HD];
__device__ float g_v[BATCH * HEADS * SEQ * HD];
__device__ float g_ao[BATCH * SEQ * DIM];

__device__ __forceinline__ unsigned tf32_of(float f) {
    unsigned u; asm("cvt.rna.tf32.f32 %0, %1;" : "=r"(u) : "f"(f)); return u;
}
__device__ __forceinline__ void mma_tf32(float* c, const unsigned* a, const unsigned* b) {
    asm volatile("mma.sync.aligned.m16n8k8.row.col.f32.tf32.tf32.f32 "
        "{%0,%1,%2,%3}, {%4,%5,%6,%7}, {%8,%9}, {%0,%1,%2,%3};"
        : "+f"(c[0]), "+f"(c[1]), "+f"(c[2]), "+f"(c[3])
        : "r"(a[0]), "r"(a[1]), "r"(a[2]), "r"(a[3]), "r"(b[0]), "r"(b[1]));
}
#define CP16(dst, src) \
    asm volatile("cp.async.cg.shared.global [%0], [%1], 16;" :: \
        "r"((unsigned)__cvta_generic_to_shared(dst)), "l"(src))

// ---------------------------------------------------------------------------
// GEMM (tf32 x3 compensation), templated epilogue.
// SEL=0: qkv = x@w^T -> scatter g_q/g_k/g_v (A = x).
// SEL=1: out = A@w^T + bias (A = g_ao, read directly from device global).
// CTA tile 128x64, 8 warps, K chunk 16, cp.async double buffer.
// ---------------------------------------------------------------------------
template<int SEL>
__global__ __launch_bounds__(256, 2) void gemm_tc(
    const float* __restrict__ Ax, const float* __restrict__ w,
    const float* __restrict__ bias, float* __restrict__ out)
{
    __shared__ __align__(16) float As[2][128][20];
    __shared__ __align__(16) float Bs[2][64][20];

    const float* A = (SEL == 0) ? Ax : g_ao;

    const int bx = blockIdx.x, by = blockIdx.y;
    const int tid = threadIdx.x, wid = tid >> 5, l = tid & 31;
    const int lq = l >> 2, lr = l & 3;
    const int wm = (wid >> 1) * 32, wn = (wid & 1) * 32;
    const int m0 = by * 128, n0 = bx * 64;
    const int lrow = tid >> 2, lkc = (tid & 3) << 2;

    float C[2][4][4] = {};

    CP16(&As[0][lrow][lkc],      &A[(size_t)(m0 + lrow) * DIM + lkc]);
    CP16(&As[0][lrow + 64][lkc], &A[(size_t)(m0 + lrow + 64) * DIM + lkc]);
    CP16(&Bs[0][lrow][lkc],      &w[(size_t)(n0 + lrow) * DIM + lkc]);
    asm volatile("cp.async.commit_group;" ::: "memory");

    const int NITER = DIM / 16;
    for (int it = 0; it < NITER; ++it) {
        if (it + 1 < NITER) {
            int k0 = (it + 1) * 16, nb = (it + 1) & 1;
            CP16(&As[nb][lrow][lkc],      &A[(size_t)(m0 + lrow) * DIM + k0 + lkc]);
            CP16(&As[nb][lrow + 64][lkc], &A[(size_t)(m0 + lrow + 64) * DIM + k0 + lkc]);
            CP16(&Bs[nb][lrow][lkc],      &w[(size_t)(n0 + lrow) * DIM + k0 + lkc]);
            asm volatile("cp.async.commit_group;" ::: "memory");
            asm volatile("cp.async.wait_group 1;" ::: "memory");
        } else {
            asm volatile("cp.async.wait_group 0;" ::: "memory");
        }
        __syncthreads();
        const int buf = it & 1;
#pragma unroll
        for (int ks = 0; ks < 2; ++ks) {
            const int kb = ks * 8;
            unsigned ah[2][4], al[2][4], bh[4][2], bl[4][2];
#pragma unroll
            for (int mt = 0; mt < 2; ++mt) {
                float a0 = As[buf][wm + mt * 16 + lq][kb + lr];
                float a1 = As[buf][wm + mt * 16 + lq + 8][kb + lr];
                float a2 = As[buf][wm + mt * 16 + lq][kb + lr + 4];
                float a3 = As[buf][wm + mt * 16 + lq + 8][kb + lr + 4];
                ah[mt][0] = tf32_of(a0); al[mt][0] = tf32_of(a0 - __uint_as_float(ah[mt][0]));
                ah[mt][1] = tf32_of(a1); al[mt][1] = tf32_of(a1 - __uint_as_float(ah[mt][1]));
                ah[mt][2] = tf32_of(a2); al[mt][2] = tf32_of(a2 - __uint_as_float(ah[mt][2]));
                ah[mt][3] = tf32_of(a3); al[mt][3] = tf32_of(a3 - __uint_as_float(ah[mt][3]));
            }
#pragma unroll
            for (int nt = 0; nt < 4; ++nt) {
                float b0 = Bs[buf][wn + nt * 8 + lq][kb + lr];
                float b1 = Bs[buf][wn + nt * 8 + lq][kb + lr + 4];
                bh[nt][0] = tf32_of(b0); bl[nt][0] = tf32_of(b0 - __uint_as_float(bh[nt][0]));
                bh[nt][1] = tf32_of(b1); bl[nt][1] = tf32_of(b1 - __uint_as_float(bh[nt][1]));
            }
#pragma unroll
            for (int mt = 0; mt < 2; ++mt)
#pragma unroll
                for (int nt = 0; nt < 4; ++nt) {
                    mma_tf32(C[mt][nt], al[mt], bh[nt]);
                    mma_tf32(C[mt][nt], ah[mt], bl[nt]);
                    mma_tf32(C[mt][nt], ah[mt], bh[nt]);
                }
        }
        __syncthreads();
    }

    if (SEL == 0) {
        const int sel = bx / HEADS, h = bx % HEADS;
        float* dst = (sel == 0) ? g_q : (sel == 1 ? g_k : g_v);
#pragma unroll
        for (int mt = 0; mt < 2; ++mt) {
            int m = m0 + wm + mt * 16 + lq;
            float* p = dst + ((size_t)((m >> 12) * HEADS + h) * SEQ + (m & 4095)) * HD;
#pragma unroll
            for (int nt = 0; nt < 4; ++nt) {
                int n = wn + nt * 8 + lr * 2;
                *(float2*)&p[n]          = make_float2(C[mt][nt][0], C[mt][nt][1]);
                *(float2*)&p[8 * HD + n] = make_float2(C[mt][nt][2], C[mt][nt][3]);
            }
        }
    } else {
#pragma unroll
        for (int mt = 0; mt < 2; ++mt) {
            int m = m0 + wm + mt * 16 + lq;
#pragma unroll
            for (int nt = 0; nt < 4; ++nt) {
                int n = n0 + wn + nt * 8 + lr * 2;
                float b0 = bias[n], b1 = bias[n + 1];
                *(float2*)&out[(size_t)m * DIM + n] =
                    make_float2(C[mt][nt][0] + b0, C[mt][nt][1] + b1);
                *(float2*)&out[(size_t)(m + 8) * DIM + n] =
                    make_float2(C[mt][nt][2] + b0, C[mt][nt][3] + b1);
            }
        }
    }
}

// ---------------------------------------------------------------------------
// Flash attention, tf32 mma, pipelined.
// Dynamic smem: 2 stages of { K[64][76] colp8-permuted, V[64][72], mask[64] }.
// colp8(d) = (d&7)*8 + (d>>3): per-nt S operands become two contiguous
// 8-float segments -> 4x LDS.128, bank-conflict-free. One barrier per tile;
// next tile's LDG.128 prefetched into registers, stored after PV.
// ---------------------------------------------------------------------------
#define KS_FLOATS (64 * 76)
#define VS_FLOATS (64 * 72)
#define STAGE_FLOATS (KS_FLOATS + VS_FLOATS + 64)
#define ATTN_SMEM_BYTES (2 * STAGE_FLOATS * 4)

__global__ __launch_bounds__(256) void attn_kernel(const int* __restrict__ mask)
{
    extern __shared__ __align__(16) float sm[];

    const int qt = blockIdx.x, bh = blockIdx.y;
    const int b = bh / HEADS, h = bh % HEADS;
    const int tid = threadIdx.x, w = tid >> 5, l = tid & 31;
    const int lq = l >> 2, lr = l & 3;

    const float* qbase = g_q + (size_t)bh * SEQ * HD;
    const float* kbase = g_k + (size_t)bh * SEQ * HD;
    const float* vbase = g_v + (size_t)bh * SEQ * HD;
    const int*   mbase = mask + b * SEQ;

    const int r0 = qt * 128 + w * 16 + lq;

    const int lc = tid >> 4, lm = tid & 15;
    const int ldd = lm << 2;
    const int kofs = (lm >> 1) + 32 * (lm & 1);   // colp8(ldd)

    unsigned aQ[8][4];
#pragma unroll
    for (int kk = 0; kk < 8; ++kk) {
        aQ[kk][0] = tf32_of(qbase[(size_t)r0 * HD + kk * 8 + lr] * QK_SCALE);
        aQ[kk][1] = tf32_of(qbase[(size_t)(r0 + 8) * HD + kk * 8 + lr] * QK_SCALE);
        aQ[kk][2] = tf32_of(qbase[(size_t)r0 * HD + kk * 8 + lr + 4] * QK_SCALE);
        aQ[kk][3] = tf32_of(qbase[(size_t)(r0 + 8) * HD + kk * 8 + lr + 4] * QK_SCALE);
    }
    const bool mq0 = mbase[r0] != 0;
    const bool mq1 = mbase[r0 + 8] != 0;

    float O[8][4] = {};
    float m0 = -FLT_MAX, m1 = -FLT_MAX, l0 = 0.f, l1 = 0.f;

    {   // prologue: tile 0 -> stage 0
        float* ks = sm; float* vs = sm + KS_FLOATS;
        int* mk = (int*)(sm + KS_FLOATS + VS_FLOATS);
#pragma unroll
        for (int u = 0; u < 4; ++u) {
            int c = lc + u * 16;
            float4 kv = *(const float4*)&kbase[(size_t)c * HD + ldd];
            float* kp = ks + c * 76 + kofs;
            kp[0]  = __uint_as_float(tf32_of(kv.x));
            kp[8]  = __uint_as_float(tf32_of(kv.y));
            kp[16] = __uint_as_float(tf32_of(kv.z));
            kp[24] = __uint_as_float(tf32_of(kv.w));
            float4 vv = *(const float4*)&vbase[(size_t)c * HD + ldd];
            float4 vt;
            vt.x = __uint_as_float(tf32_of(vv.x)); vt.y = __uint_as_float(tf32_of(vv.y));
            vt.z = __uint_as_float(tf32_of(vv.z)); vt.w = __uint_as_float(tf32_of(vv.w));
            *(float4*)&vs[c * 72 + ldd] = vt;
        }
        if (tid < 64) mk[tid] = mbase[tid];
    }
    __syncthreads();

    for (int kt = 0; kt < SEQ / 64; ++kt) {
        const int s = kt & 1;
        float* ks = sm + s * STAGE_FLOATS;
        float* vs = ks + KS_FLOATS;
        int* mk = (int*)(vs + VS_FLOATS);
        const bool pf = (kt + 1 < SEQ / 64);

        float4 kreg[4], vreg[4];
        int mreg = 0;
        if (pf) {
            const size_t nb = (size_t)(kt + 1) * 64;
#pragma unroll
            for (int u = 0; u < 4; ++u) {
                int c = lc + u * 16;
                kreg[u] = *(const float4*)&kbase[(nb + c) * HD + ldd];
                vreg[u] = *(const float4*)&vbase[(nb + c) * HD + ldd];
            }
            if (tid < 64) mreg = mbase[nb + tid];
        }

        float sc[8][4];
#pragma unroll
        for (int nt = 0; nt < 8; ++nt) {
            sc[nt][0] = sc[nt][1] = sc[nt][2] = sc[nt][3] = 0.f;
            const float* krow = ks + (nt * 8 + lq) * 76;
            float4 a0 = *(const float4*)(krow + lr * 8);
            float4 a1 = *(const float4*)(krow + lr * 8 + 4);
            float4 b0 = *(const float4*)(krow + (lr + 4) * 8);
            float4 b1 = *(const float4*)(krow + (lr + 4) * 8 + 4);
            float segA[8] = {a0.x, a0.y, a0.z, a0.w, a1.x, a1.y, a1.z, a1.w};
            float segB[8] = {b0.x, b0.y, b0.z, b0.w, b1.x, b1.y, b1.z, b1.w};
#pragma unroll
            for (int kk = 0; kk < 8; ++kk) {
                unsigned bk[2] = {__float_as_uint(segA[kk]), __float_as_uint(segB[kk])};
                mma_tf32(sc[nt], aQ[kk], bk);
            }
        }

        float t0 = -FLT_MAX, t1 = -FLT_MAX;
#pragma unroll
        for (int nt = 0; nt < 8; ++nt) {
            int c0 = nt * 8 + lr * 2;
            bool mc0 = mk[c0] != 0, mc1 = mk[c0 + 1] != 0;
            if (!(mq0 && mc0)) sc[nt][0] = -FLT_MAX;
            if (!(mq0 && mc1)) sc[nt][1] = -FLT_MAX;
            if (!(mq1 && mc0)) sc[nt][2] = -FLT_MAX;
            if (!(mq1 && mc1)) sc[nt][3] = -FLT_MAX;
            t0 = fmaxf(t0, fmaxf(sc[nt][0], sc[nt][1]));
            t1 = fmaxf(t1, fmaxf(sc[nt][2], sc[nt][3]));
        }
        t0 = fmaxf(t0, __shfl_xor_sync(0xffffffffu, t0, 1));
        t0 = fmaxf(t0, __shfl_xor_sync(0xffffffffu, t0, 2));
        t1 = fmaxf(t1, __shfl_xor_sync(0xffffffffu, t1, 1));
        t1 = fmaxf(t1, __shfl_xor_sync(0xffffffffu, t1, 2));

        float mn0 = fmaxf(m0, t0), mn1 = fmaxf(m1, t1);
        float al0 = __expf(m0 - mn0), al1 = __expf(m1 - mn1);
        m0 = mn0; m1 = mn1;

        float ps0 = 0.f, ps1 = 0.f;
#pragma unroll
        for (int nt = 0; nt < 8; ++nt) {
            sc[nt][0] = __expf(sc[nt][0] - mn0);
            sc[nt][1] = __expf(sc[nt][1] - mn0);
            sc[nt][2] = __expf(sc[nt][2] - mn1);
            sc[nt][3] = __expf(sc[nt][3] - mn1);
            ps0 += sc[nt][0] + sc[nt][1];
            ps1 += sc[nt][2] + sc[nt][3];
        }
        ps0 += __shfl_xor_sync(0xffffffffu, ps0, 1);
        ps0 += __shfl_xor_sync(0xffffffffu, ps0, 2);
        ps1 += __shfl_xor_sync(0xffffffffu, ps1, 1);
        ps1 += __shfl_xor_sync(0xffffffffu, ps1, 2);
        l0 = l0 * al0 + ps0;
        l1 = l1 * al1 + ps1;

#pragma unroll
        for (int nt = 0; nt < 8; ++nt) {
            O[nt][0] *= al0; O[nt][1] *= al0;
            O[nt][2] *= al1; O[nt][3] *= al1;
        }

        const int srcA = (l & ~3) + (lr >> 1);
        const bool par = (lr & 1) != 0;
#pragma unroll
        for (int kk = 0; kk < 8; ++kk) {
            float x0 = __shfl_sync(0xffffffffu, sc[kk][0], srcA);
            float x1 = __shfl_sync(0xffffffffu, sc[kk][1], srcA);
            float x2 = __shfl_sync(0xffffffffu, sc[kk][2], srcA);
            float x3 = __shfl_sync(0xffffffffu, sc[kk][3], srcA);
            float y0 = __shfl_sync(0xffffffffu, sc[kk][0], srcA + 2);
            float y1 = __shfl_sync(0xffffffffu, sc[kk][1], srcA + 2);
            float y2 = __shfl_sync(0xffffffffu, sc[kk][2], srcA + 2);
            float y3 = __shfl_sync(0xffffffffu, sc[kk][3], srcA + 2);
            unsigned aP[4];
            aP[0] = tf32_of(par ? x1 : x0);
            aP[1] = tf32_of(par ? x3 : x2);
            aP[2] = tf32_of(par ? y1 : y0);
            aP[3] = tf32_of(par ? y3 : y2);
            const float* vr0 = vs + (kk * 8 + lr) * 72;
            const float* vr1 = vs + (kk * 8 + lr + 4) * 72;
#pragma unroll
            for (int nt = 0; nt < 8; ++nt) {
                unsigned bv[2] = {__float_as_uint(vr0[nt * 8 + lq]),
                                  __float_as_uint(vr1[nt * 8 + lq])};
                mma_tf32(O[nt], aP, bv);
            }
        }

        if (pf) {
            float* ks2 = sm + (s ^ 1) * STAGE_FLOATS;
            float* vs2 = ks2 + KS_FLOATS;
            int* mk2 = (int*)(vs2 + VS_FLOATS);
#pragma unroll
            for (int u = 0; u < 4; ++u) {
                int c = lc + u * 16;
                float* kp = ks2 + c * 76 + kofs;
                kp[0]  = __uint_as_float(tf32_of(kreg[u].x));
                kp[8]  = __uint_as_float(tf32_of(kreg[u].y));
                kp[16] = __uint_as_float(tf32_of(kreg[u].z));
                kp[24] = __uint_as_float(tf32_of(kreg[u].w));
                float4 vt;
                vt.x = __uint_as_float(tf32_of(vreg[u].x));
                vt.y = __uint_as_float(tf32_of(vreg[u].y));
                vt.z = __uint_as_float(tf32_of(vreg[u].z));
                vt.w = __uint_as_float(tf32_of(vreg[u].w));
                *(float4*)&vs2[c * 72 + ldd] = vt;
            }
            if (tid < 64) mk2[tid] = mreg;
        }
        __syncthreads();
    }

    const float inv0 = 1.f / l0, inv1 = 1.f / l1;
    float* orow0 = g_ao + ((size_t)b * SEQ + r0) * DIM + h * HD;
    float* orow1 = orow0 + 8 * DIM;
#pragma unroll
    for (int nt = 0; nt < 8; ++nt) {
        int c = nt * 8 + lr * 2;
        *(float2*)&orow0[c] = make_float2(O[nt][0] * inv0, O[nt][1] * inv0);
        *(float2*)&orow1[c] = make_float2(O[nt][2] * inv1, O[nt][3] * inv1);
    }
}

// ---------------------------------------------------------------------------
extern "C" void kernel_launch(void* const* d_in, const int* in_sizes, int n_in,
                              void* d_out, int out_size)
{
    const float* x      = (const float*)d_in[0];
    const int*   mask   = (const int*)d_in[1];
    const float* w_qkv  = (const float*)d_in[2];
    const float* w_proj = (const float*)d_in[3];
    const float* b_proj = (const float*)d_in[4];
    float*       out    = (float*)d_out;

    cudaFuncSetAttribute(attn_kernel,
        cudaFuncAttributeMaxDynamicSharedMemorySize, ATTN_SMEM_BYTES);

    dim3 g1(3 * DIM / 64, (BATCH * SEQ) / 128);
    gemm_tc<0><<<g1, 256>>>(x, w_qkv, nullptr, nullptr);

    dim3 g2(SEQ / 128, BATCH * HEADS);
    attn_kernel<<<g2, 256, ATTN_SMEM_BYTES>>>(mask);

    dim3 g3(DIM / 64, (BATCH * SEQ) / 128);
    gemm_tc<1><<<g3, 256>>>(nullptr, w_proj, b_proj, out);
}